// round 11
// baseline (speedup 1.0000x reference)
#include <cuda_runtime.h>
#include <cstdint>

#define NROWS  (1u << 20)
#define KTOP   1024
#define ECAP   8192
#define KEYNEG 0x31914AD7u        // fkey(-1e9f)
#define BIN0   0xBE80u
#define TOPBIN 0xBF7Fu
#define TILES  8
#define TROWS  32
#define GBLK   16u                // blocks in k_rest

// ---------------- scratch (module-load allocations, allowed) ----------------
__device__ unsigned            g_key[NROWS];
__device__ unsigned            g_cntT;
__device__ unsigned            g_sync0, g_sync1, g_sync2;
__device__ uint2               g_T[ECAP];
__device__ uint2               g_A[KTOP];
__device__ uint2               g_E2[ECAP];
__device__ unsigned            g_order[KTOP];
__device__ float4              g_boxes[KTOP];
__device__ float4              g_info[KTOP];
__device__ unsigned long long  g_rowNZ[16];
__device__ __align__(16) unsigned long long g_M[KTOP * 16];

// ---------------- K1: score kernel -> key + top-bin candidates --------------
__global__ void __launch_bounds__(256) k_score(const float* __restrict__ pred) {
    __shared__ float4 sbuf[2][TROWS * 85 / 4];
    unsigned t = threadIdx.x;
    size_t blockRow0 = (size_t)blockIdx.x * (TILES * TROWS);
    const float4* gsrc = reinterpret_cast<const float4*>(pred)
                         + blockRow0 * 85 / 4;

    {
        float4* dst = sbuf[0];
        #pragma unroll
        for (int k = 0; k < 3; k++) {
            unsigned i = t + (unsigned)k * 256u;
            if (i < 680u) {
                unsigned sa = (unsigned)__cvta_generic_to_shared(dst + i);
                asm volatile("cp.async.cg.shared.global [%0], [%1], 16;\n"
                             :: "r"(sa), "l"(gsrc + i));
            }
        }
        asm volatile("cp.async.commit_group;\n");
    }

    unsigned row = t >> 3, seg = t & 7u;
    #pragma unroll
    for (int tile = 0; tile < TILES; tile++) {
        if (tile + 1 < TILES) {
            float4* dst = sbuf[(tile + 1) & 1];
            const float4* src = gsrc + (size_t)(tile + 1) * 680u;
            #pragma unroll
            for (int k = 0; k < 3; k++) {
                unsigned i = t + (unsigned)k * 256u;
                if (i < 680u) {
                    unsigned sa = (unsigned)__cvta_generic_to_shared(dst + i);
                    asm volatile("cp.async.cg.shared.global [%0], [%1], 16;\n"
                                 :: "r"(sa), "l"(src + i));
                }
            }
            asm volatile("cp.async.commit_group;\n");
            asm volatile("cp.async.wait_group 1;\n");
        } else {
            asm volatile("cp.async.wait_group 0;\n");
        }
        __syncthreads();

        const float* s = reinterpret_cast<const float*>(sbuf[tile & 1]);
        const float* r = s + row * 85u;
        unsigned best = __float_as_uint(r[5 + seg * 10]);
        #pragma unroll
        for (int j = 1; j < 10; j++)
            best = max(best, __float_as_uint(r[5 + seg * 10 + j]));
        #pragma unroll
        for (int d = 4; d; d >>= 1)
            best = max(best, __shfl_down_sync(0xFFFFFFFFu, best, d, 8));
        if (seg == 0u) {
            float obj = r[4];
            float conf = __fmul_rn(obj, __uint_as_float(best));
            unsigned key = (conf >= 0.25f) ? (__float_as_uint(obj) | 0x80000000u)
                                           : KEYNEG;
            unsigned grow = (unsigned)(blockRow0 + (size_t)tile * TROWS + row);
            g_key[grow] = key;
            if ((key >> 16) == TOPBIN) {
                unsigned pn = atomicAdd(&g_cntT, 1u);
                if (pn < ECAP) g_T[pn] = make_uint2(key, grow);
            }
        }
        __syncthreads();
    }
}

// ---- single-warp suffix-scan boundary finder over 256 smem bins ------------
__device__ __forceinline__ void sufscan_find(const unsigned* hist, unsigned K,
                                             unsigned* outBin, unsigned* outK) {
    unsigned t = threadIdx.x;
    if (t < 32u) {
        unsigned h[8], s[8], acc = 0u;
        #pragma unroll
        for (int i = 7; i >= 0; i--) { h[i] = hist[t * 8u + (unsigned)i]; acc += h[i]; s[i] = acc; }
        unsigned suf = acc;
        #pragma unroll
        for (int off = 1; off < 32; off <<= 1) {
            unsigned v = __shfl_down_sync(0xFFFFFFFFu, suf, off);
            if (t + (unsigned)off < 32u) suf += v;
        }
        unsigned base = suf - acc;
        #pragma unroll
        for (int i = 0; i < 8; i++) {
            unsigned Sinc = s[i] + base, Sexc = Sinc - h[i];
            if (Sexc < K && Sinc >= K) { *outBin = t * 8u + (unsigned)i; *outK = K - Sexc; }
        }
    }
}

// ---------------- K2: fused select + gather + IoU + NMS + output ------------
__global__ void __launch_bounds__(1024) k_rest(const float* __restrict__ pred,
                                               float* __restrict__ out,
                                               int keepmode) {
    extern __shared__ __align__(16) unsigned long long Ms[];   // 1024*17 u64
    __shared__ float4 sb[KTOP];
    __shared__ unsigned hist[256];
    __shared__ unsigned eq[128];
    __shared__ unsigned validw_sh[32];
    __shared__ unsigned long long keepw[16], rowNZsh[16], remv[16], vmArr[16];
    __shared__ unsigned long long tmpOr[32];
    __shared__ unsigned sh_bin, sh_K, sh_cntG, sh_cntEq, sh_cA, sh_cE;
    unsigned t = threadIdx.x;
    unsigned bid = blockIdx.x;

    // ===================== phase S: selection (block 0 only) ================
    if (bid == 0u) {
        unsigned long long* pA = Ms;
        unsigned long long* pB = Ms + KTOP;

        unsigned cntT = g_cntT;
        bool fb = !(cntT >= KTOP && cntT <= (unsigned)ECAP);
        const uint2* src;
        unsigned CE, K2, b1v, cntA;

        if (!fb) {
            src = g_T; CE = cntT; K2 = KTOP; b1v = TOPBIN; cntA = 0u;
        } else {
            if (t < 256u) hist[t] = 0u;
            if (t == 0u) { sh_cA = 0u; sh_cE = 0u; }
            __syncthreads();
            const uint4* kp = reinterpret_cast<const uint4*>(g_key);
            for (unsigned i = t; i < NROWS / 4; i += 1024u) {
                uint4 k4 = kp[i];
                unsigned b;
                b = (k4.x >> 16) - BIN0; if (b < 256u) atomicAdd(&hist[b], 1u);
                b = (k4.y >> 16) - BIN0; if (b < 256u) atomicAdd(&hist[b], 1u);
                b = (k4.z >> 16) - BIN0; if (b < 256u) atomicAdd(&hist[b], 1u);
                b = (k4.w >> 16) - BIN0; if (b < 256u) atomicAdd(&hist[b], 1u);
            }
            __syncthreads();
            sufscan_find(hist, KTOP, &sh_bin, &sh_K);
            __syncthreads();
            unsigned b1 = sh_bin + BIN0;
            unsigned Kb = sh_K;
            for (unsigned i = t; i < NROWS; i += 1024u) {
                unsigned key = g_key[i];
                unsigned bin = key >> 16;
                if (bin > b1 && bin <= TOPBIN) {
                    unsigned pn = atomicAdd(&sh_cA, 1u);
                    if (pn < KTOP) g_A[pn] = make_uint2(key, i);
                } else if (bin == b1) {
                    unsigned pn = atomicAdd(&sh_cE, 1u);
                    if (pn < ECAP) g_E2[pn] = make_uint2(key, i);
                }
            }
            __syncthreads();
            src = g_E2; CE = min(sh_cE, (unsigned)ECAP);
            K2 = Kb; b1v = b1; cntA = min(sh_cA, (unsigned)KTOP);
        }

        // pass A: hist of key bits[8:16)
        if (t < 256u) hist[t] = 0u;
        if (t == 0u) { sh_cntG = 0u; sh_cntEq = 0u; }
        __syncthreads();
        for (unsigned e = t; e < CE; e += 1024u)
            atomicAdd(&hist[(src[e].x >> 8) & 0xFFu], 1u);
        __syncthreads();
        sufscan_find(hist, K2, &sh_bin, &sh_K);
        __syncthreads();
        unsigned bh = sh_bin, K3 = sh_K;

        // pass B: hist of low 8 bits within sub-bin bh
        if (t < 256u) hist[t] = 0u;
        __syncthreads();
        for (unsigned e = t; e < CE; e += 1024u) {
            unsigned k = src[e].x;
            if (((k >> 8) & 0xFFu) == bh) atomicAdd(&hist[k & 0xFFu], 1u);
        }
        __syncthreads();
        sufscan_find(hist, K3, &sh_bin, &sh_K);
        __syncthreads();
        unsigned VkLow = (bh << 8) | sh_bin;
        unsigned teq = sh_K;
        unsigned Vk  = (b1v << 16) | VkLow;

        // classify
        if (t < cntA) {
            uint2 a = g_A[t];
            pA[t] = ((unsigned long long)a.x << 32) | (unsigned)(~a.y);
        }
        for (unsigned e = t; e < CE; e += 1024u) {
            uint2 v = src[e];
            unsigned low = v.x & 0xFFFFu;
            if (low > VkLow) {
                unsigned p = atomicAdd(&sh_cntG, 1u);
                pA[cntA + p] = ((unsigned long long)v.x << 32) | (unsigned)(~v.y);
            } else if (low == VkLow) {
                unsigned p = atomicAdd(&sh_cntEq, 1u);
                if (p < 128u) eq[p] = v.y;
            }
        }
        __syncthreads();
        unsigned cntG = sh_cntG, cntEq = min(sh_cntEq, 128u);

        // sort ties ascending by index
        if (cntEq <= 32u) {
            if (t < 32u) {
                unsigned val = (t < cntEq) ? eq[t] : 0xFFFFFFFFu;
                #pragma unroll
                for (unsigned kk = 2; kk <= 32; kk <<= 1)
                    for (unsigned j = kk >> 1; j > 0; j >>= 1) {
                        unsigned other = __shfl_xor_sync(0xFFFFFFFFu, val, j);
                        bool up   = ((t & kk) == 0u);
                        bool lowp = ((t & j) == 0u);
                        unsigned mx = max(val, other), mn = min(val, other);
                        val = (lowp == up) ? mn : mx;
                    }
                eq[t] = val;
            }
            __syncthreads();
        } else {
            if (t < 128u && t >= cntEq) eq[t] = 0xFFFFFFFFu;
            __syncthreads();
            for (unsigned kk = 2; kk <= 128; kk <<= 1)
                for (unsigned j = kk >> 1; j > 0; j >>= 1) {
                    if (t < 128u) {
                        unsigned ixj = t ^ j;
                        if (ixj > t) {
                            unsigned a = eq[t], b = eq[ixj];
                            bool up = ((t & kk) == 0u);
                            if ((a > b) == up) { eq[t] = b; eq[ixj] = a; }
                        }
                    }
                    __syncthreads();
                }
        }
        if (t < teq)
            pA[cntA + cntG + t] = ((unsigned long long)Vk << 32) | (unsigned)(~eq[t]);
        __syncthreads();

        // bitonic 1024 descending by (key,~idx); shfl for j<32
        unsigned long long val = pA[t];
        int cur = 1;
        for (unsigned kk = 2; kk <= KTOP; kk <<= 1) {
            for (unsigned j = kk >> 1; j > 0; j >>= 1) {
                bool up   = ((t & kk) == 0u);
                bool lowp = ((t & j) == 0u);
                unsigned long long other;
                if (j >= 32u) {
                    unsigned long long* w = cur ? pB : pA;
                    w[t] = val;
                    __syncthreads();
                    other = w[t ^ j];
                    cur ^= 1;
                } else {
                    other = __shfl_xor_sync(0xFFFFFFFFu, val, j);
                }
                unsigned long long mx = (val > other) ? val : other;
                unsigned long long mn = (val > other) ? other : val;
                val = (lowp == up) ? mx : mn;
            }
        }

        unsigned key = (unsigned)(val >> 32);
        unsigned idx = ~(unsigned)val;
        int valid = (key >= (BIN0 << 16)) ? 1 : 0;
        unsigned bal = __ballot_sync(0xFFFFFFFFu, valid);
        if ((t & 31u) == 0u) validw_sh[t >> 5] = bal;
        g_order[t] = idx;
        __threadfence();
        __syncthreads();
        if (t == 0u) atomicExch(&g_sync0, 1u);
    } else {
        if (t == 0u)
            while (atomicAdd(&g_sync0, 0u) == 0u) __nanosleep(128);
        __syncthreads();
        __threadfence();
    }

    // ===================== phase G: gather 64 slots per block ===============
    if (t < 512u) {
        unsigned slot = bid * 64u + (t >> 3);
        unsigned seg = t & 7u;
        unsigned idx = g_order[slot];
        const float* r = pred + (size_t)idx * 85u;
        unsigned best = __float_as_uint(__ldg(r + 5 + seg * 10));
        unsigned bi   = seg * 10u;
        #pragma unroll
        for (int j = 1; j < 10; j++) {
            unsigned v = __float_as_uint(__ldg(r + 5 + seg * 10 + j));
            if (v > best) { best = v; bi = seg * 10u + (unsigned)j; }
        }
        #pragma unroll
        for (int d = 4; d; d >>= 1) {
            unsigned ob = __shfl_down_sync(0xFFFFFFFFu, best, d, 8);
            unsigned oi = __shfl_down_sync(0xFFFFFFFFu, bi, d, 8);
            if (ob > best || (ob == best && oi < bi)) { best = ob; bi = oi; }
        }
        if (seg == 0u) {
            float cx = __ldg(r), cy = __ldg(r + 1), w = __ldg(r + 2),
                  h = __ldg(r + 3), obj = __ldg(r + 4);
            float c = __uint_as_float(best);
            float hw = __fmul_rn(w, 0.5f), hh = __fmul_rn(h, 0.5f);
            g_boxes[slot] = make_float4(__fsub_rn(cx, hw), __fsub_rn(cy, hh),
                                        __fadd_rn(cx, hw), __fadd_rn(cy, hh));
            g_info[slot]  = make_float4(obj, c, (float)bi, 0.0f);
        }
    }
    __threadfence();
    __syncthreads();
    if (t == 0u) {
        atomicAdd(&g_sync1, 1u);
        while (atomicAdd(&g_sync1, 0u) < GBLK) __nanosleep(64);
    }
    __syncthreads();
    __threadfence();

    // ===================== phase I: IoU rows [bid*64, bid*64+64) ============
    sb[t] = g_boxes[t];
    __syncthreads();
    {
        unsigned w = bid * 1024u + t;
        unsigned i = w >> 4, blk = w & 15u;
        float4 bi = sb[i];
        float ai = __fmul_rn(__fsub_rn(bi.z, bi.x), __fsub_rn(bi.w, bi.y));
        unsigned long long bits = 0ull;
        unsigned jbase = blk * 64u;
        #pragma unroll 4
        for (int jj = 0; jj < 64; jj++) {
            float4 bj = sb[jbase + jj];
            float aj = __fmul_rn(__fsub_rn(bj.z, bj.x), __fsub_rn(bj.w, bj.y));
            float ltx = fmaxf(bi.x, bj.x), lty = fmaxf(bi.y, bj.y);
            float rbx = fminf(bi.z, bj.z), rby = fminf(bi.w, bj.w);
            float wx = fmaxf(__fsub_rn(rbx, ltx), 0.0f);
            float wy = fmaxf(__fsub_rn(rby, lty), 0.0f);
            float inter = __fmul_rn(wx, wy);
            float uni = __fsub_rn(__fadd_rn(ai, aj), inter);
            float iou = __fdiv_rn(inter, fmaxf(uni, 1e-9f));
            bits |= ((unsigned long long)(iou > 0.65f)) << jj;
        }
        g_M[(size_t)i * 16 + blk] = bits;

        unsigned long long selfm = (blk == (i >> 6)) ? (1ull << (i & 63u)) : 0ull;
        int nz = ((bits & ~selfm) != 0ull);
        unsigned bal = __ballot_sync(0xFFFFFFFFu, nz);
        unsigned lane = t & 31u;
        if (lane == 0u && (bal & 0xFFFFu))
            atomicOr(&g_rowNZ[i >> 6], 1ull << (i & 63u));
        if (lane == 16u && (bal >> 16))
            atomicOr(&g_rowNZ[i >> 6], 1ull << (i & 63u));
    }
    __threadfence();
    __syncthreads();
    if (t == 0u) atomicAdd(&g_sync2, 1u);
    if (bid != 0u) return;

    // ===================== phase N (block 0): NMS + output ==================
    if (t == 0u)
        while (atomicAdd(&g_sync2, 0u) < GBLK) __nanosleep(64);
    __syncthreads();
    __threadfence();

    {   // stage 128KB matrix into stride-17 smem
        const uint4* gm4 = reinterpret_cast<const uint4*>(g_M);
        #pragma unroll
        for (unsigned x4 = t; x4 < 8192u; x4 += 1024u) {
            uint4 v = gm4[x4];
            unsigned row = x4 >> 3, p = x4 & 7u;
            Ms[(size_t)row * 17u + 2u * p]      = ((unsigned long long)v.y << 32) | v.x;
            Ms[(size_t)row * 17u + 2u * p + 1u] = ((unsigned long long)v.w << 32) | v.z;
        }
    }
    if (t < 16u) {
        vmArr[t]   = (unsigned long long)validw_sh[2u * t]
                   | ((unsigned long long)validw_sh[2u * t + 1u] << 32);
        rowNZsh[t] = g_rowNZ[t];
        remv[t]    = 0ull;
    }
    __syncthreads();

    for (unsigned b = 0; b < 16u; b++) {
        if (t < 32u) {
            unsigned long long vmb = vmArr[b], rvb = remv[b], nzb = rowNZsh[b];
            unsigned long long avail = vmb & ~rvb;
            unsigned long long keepmask = avail & ~nzb;
            unsigned long long serialm = avail & nzb;
            unsigned rowbase = b * 64u;
            if (serialm) {
                #pragma unroll
                for (int q = 0; q < 4; q++) {
                    if (!((serialm >> (q * 16)) & 0xFFFFull)) continue;
                    unsigned long long col[16];
                    #pragma unroll
                    for (int jj = 0; jj < 16; jj++)
                        col[jj] = Ms[(size_t)(rowbase + (unsigned)(q * 16 + jj)) * 17u + b];
                    #pragma unroll
                    for (int jj = 0; jj < 16; jj++) {
                        int j = q * 16 + jj;
                        if ((serialm >> j) & 1ull) {
                            unsigned long long below = (1ull << j) - 1ull;
                            if ((keepmask & col[jj] & below) == 0ull)
                                keepmask |= 1ull << j;
                        }
                    }
                }
            }
            if (t == 0u) keepw[b] = keepmask;
        }
        __syncthreads();
        // atomic-free cross-block suppression OR
        {
            unsigned long long km = keepw[b];
            unsigned c = t >> 6, j = t & 63u;
            unsigned long long acc = ((km >> j) & 1ull)
                                   ? Ms[(size_t)(b * 64u + j) * 17u + c] : 0ull;
            #pragma unroll
            for (int off = 16; off; off >>= 1)
                acc |= __shfl_down_sync(0xFFFFFFFFu, acc, off);
            if ((t & 31u) == 0u) tmpOr[t >> 5] = acc;
        }
        __syncthreads();
        if (t < 16u) remv[t] |= tmpOr[2u * t] | tmpOr[2u * t + 1u];
        __syncthreads();
    }

    // output
    {
        unsigned slot = t;
        int keep = (int)((keepw[slot >> 6] >> (slot & 63u)) & 1ull);
        float m = keep ? 1.0f : 0.0f;
        float4 b = g_boxes[slot];
        float4 inf = g_info[slot];
        float* o = out + (size_t)slot * 7;
        o[0] = __fmul_rn(b.x, m);  o[1] = __fmul_rn(b.y, m);
        o[2] = __fmul_rn(b.z, m);  o[3] = __fmul_rn(b.w, m);
        o[4] = __fmul_rn(inf.x, m); o[5] = __fmul_rn(inf.y, m);
        o[6] = __fmul_rn(inf.z, m);
        if (keepmode == 0)
            out[KTOP * 7 + slot] = m;
        else
            ((unsigned char*)(out + KTOP * 7))[slot] = (unsigned char)keep;
    }

    // reset scratch for next graph replay
    if (t < 16u) g_rowNZ[t] = 0ull;
    if (t == 0u) { g_sync0 = 0u; g_sync1 = 0u; g_sync2 = 0u; g_cntT = 0u; }
}

// ---------------- host ----------------
extern "C" void kernel_launch(void* const* d_in, const int* in_sizes, int n_in,
                              void* d_out, int out_size) {
    const float* pred = (const float*)d_in[0];
    float* out = (float*)d_out;
    int keepmode = 0;
    if (out_size == KTOP * 7 + KTOP / 4) keepmode = 1;

    k_score<<<NROWS / (TILES * TROWS), 256>>>(pred);          // 1
    size_t rest_smem = (size_t)KTOP * 17 * 8;                 // 139264B
    cudaFuncSetAttribute(k_rest, cudaFuncAttributeMaxDynamicSharedMemorySize,
                         (int)rest_smem);
    k_rest<<<GBLK, 1024, rest_smem>>>(pred, out, keepmode);   // 2 (launch #4 overall -> ncu)
}

// round 12
// speedup vs baseline: 1.2273x; 1.2273x over previous
#include <cuda_runtime.h>
#include <cstdint>

#define NROWS  (1u << 20)
#define KTOP   1024
#define ECAP   8192
#define KEYNEG 0x31914AD7u        // fkey(-1e9f)
#define BIN0   0xBE80u
#define TOPBIN 0xBF7Fu
#define TILES  8
#define TROWS  32
#define GBLK   64u                // blocks in k_rest (1/SM, co-resident)

// ---------------- scratch (module-load allocations, allowed) ----------------
__device__ unsigned            g_key[NROWS];
__device__ unsigned            g_cntT;
__device__ unsigned            g_sync0, g_sync1, g_sync2;
__device__ uint2               g_T[ECAP];
__device__ uint2               g_A[KTOP];
__device__ uint2               g_E2[ECAP];
__device__ unsigned            g_order[KTOP];
__device__ float4              g_boxes[KTOP];
__device__ float4              g_info[KTOP];
__device__ unsigned            g_validw[32];
__device__ unsigned long long  g_rowNZ[16];
__device__ __align__(16) unsigned long long g_M[KTOP * 16];

// ---------------- K1: score kernel -> key + top-bin candidates --------------
__global__ void __launch_bounds__(256) k_score(const float* __restrict__ pred) {
    __shared__ float4 sbuf[2][TROWS * 85 / 4];
    unsigned t = threadIdx.x;
    size_t blockRow0 = (size_t)blockIdx.x * (TILES * TROWS);
    const float4* gsrc = reinterpret_cast<const float4*>(pred)
                         + blockRow0 * 85 / 4;

    {
        float4* dst = sbuf[0];
        #pragma unroll
        for (int k = 0; k < 3; k++) {
            unsigned i = t + (unsigned)k * 256u;
            if (i < 680u) {
                unsigned sa = (unsigned)__cvta_generic_to_shared(dst + i);
                asm volatile("cp.async.cg.shared.global [%0], [%1], 16;\n"
                             :: "r"(sa), "l"(gsrc + i));
            }
        }
        asm volatile("cp.async.commit_group;\n");
    }

    unsigned row = t >> 3, seg = t & 7u;
    #pragma unroll
    for (int tile = 0; tile < TILES; tile++) {
        if (tile + 1 < TILES) {
            float4* dst = sbuf[(tile + 1) & 1];
            const float4* src = gsrc + (size_t)(tile + 1) * 680u;
            #pragma unroll
            for (int k = 0; k < 3; k++) {
                unsigned i = t + (unsigned)k * 256u;
                if (i < 680u) {
                    unsigned sa = (unsigned)__cvta_generic_to_shared(dst + i);
                    asm volatile("cp.async.cg.shared.global [%0], [%1], 16;\n"
                                 :: "r"(sa), "l"(src + i));
                }
            }
            asm volatile("cp.async.commit_group;\n");
            asm volatile("cp.async.wait_group 1;\n");
        } else {
            asm volatile("cp.async.wait_group 0;\n");
        }
        __syncthreads();

        const float* s = reinterpret_cast<const float*>(sbuf[tile & 1]);
        const float* r = s + row * 85u;
        unsigned best = __float_as_uint(r[5 + seg * 10]);
        #pragma unroll
        for (int j = 1; j < 10; j++)
            best = max(best, __float_as_uint(r[5 + seg * 10 + j]));
        #pragma unroll
        for (int d = 4; d; d >>= 1)
            best = max(best, __shfl_down_sync(0xFFFFFFFFu, best, d, 8));
        if (seg == 0u) {
            float obj = r[4];
            float conf = __fmul_rn(obj, __uint_as_float(best));
            unsigned key = (conf >= 0.25f) ? (__float_as_uint(obj) | 0x80000000u)
                                           : KEYNEG;
            unsigned grow = (unsigned)(blockRow0 + (size_t)tile * TROWS + row);
            g_key[grow] = key;
            if ((key >> 16) == TOPBIN) {
                unsigned pn = atomicAdd(&g_cntT, 1u);
                if (pn < ECAP) g_T[pn] = make_uint2(key, grow);
            }
        }
        __syncthreads();
    }
}

// ---- single-warp suffix-scan boundary finder over 256 smem bins ------------
__device__ __forceinline__ void sufscan_find(const unsigned* hist, unsigned K,
                                             unsigned* outBin, unsigned* outK) {
    unsigned t = threadIdx.x;
    if (t < 32u) {
        unsigned h[8], s[8], acc = 0u;
        #pragma unroll
        for (int i = 7; i >= 0; i--) { h[i] = hist[t * 8u + (unsigned)i]; acc += h[i]; s[i] = acc; }
        unsigned suf = acc;
        #pragma unroll
        for (int off = 1; off < 32; off <<= 1) {
            unsigned v = __shfl_down_sync(0xFFFFFFFFu, suf, off);
            if (t + (unsigned)off < 32u) suf += v;
        }
        unsigned base = suf - acc;
        #pragma unroll
        for (int i = 0; i < 8; i++) {
            unsigned Sinc = s[i] + base, Sexc = Sinc - h[i];
            if (Sexc < K && Sinc >= K) { *outBin = t * 8u + (unsigned)i; *outK = K - Sexc; }
        }
    }
}

// ---------------- K2: fused select + gather + IoU + NMS + output ------------
__global__ void __launch_bounds__(1024) k_rest(const float* __restrict__ pred,
                                               float* __restrict__ out,
                                               int keepmode) {
    extern __shared__ __align__(16) unsigned long long Ms[];   // 1024*17 u64
    __shared__ float4 sb[KTOP];
    __shared__ unsigned hist[256];
    __shared__ unsigned eq[128];
    __shared__ unsigned validw_sh[32];
    __shared__ unsigned long long keepw[16], rowNZsh[16], remv[16], vmArr[16];
    __shared__ unsigned long long tmpOr[32];
    __shared__ unsigned sh_bin, sh_K, sh_cntG, sh_cntEq, sh_cA, sh_cE;
    unsigned t = threadIdx.x;
    unsigned bid = blockIdx.x;

    // ===================== phase S: selection (block 0 only) ================
    if (bid == 0u) {
        unsigned long long* pA = Ms;
        unsigned long long* pB = Ms + KTOP;

        unsigned cntT = g_cntT;
        bool fb = !(cntT >= KTOP && cntT <= (unsigned)ECAP);
        const uint2* src;
        unsigned CE, K2, b1v, cntA;

        if (!fb) {
            src = g_T; CE = cntT; K2 = KTOP; b1v = TOPBIN; cntA = 0u;
        } else {
            if (t < 256u) hist[t] = 0u;
            if (t == 0u) { sh_cA = 0u; sh_cE = 0u; }
            __syncthreads();
            const uint4* kp = reinterpret_cast<const uint4*>(g_key);
            for (unsigned i = t; i < NROWS / 4; i += 1024u) {
                uint4 k4 = kp[i];
                unsigned b;
                b = (k4.x >> 16) - BIN0; if (b < 256u) atomicAdd(&hist[b], 1u);
                b = (k4.y >> 16) - BIN0; if (b < 256u) atomicAdd(&hist[b], 1u);
                b = (k4.z >> 16) - BIN0; if (b < 256u) atomicAdd(&hist[b], 1u);
                b = (k4.w >> 16) - BIN0; if (b < 256u) atomicAdd(&hist[b], 1u);
            }
            __syncthreads();
            sufscan_find(hist, KTOP, &sh_bin, &sh_K);
            __syncthreads();
            unsigned b1 = sh_bin + BIN0;
            unsigned Kb = sh_K;
            for (unsigned i = t; i < NROWS; i += 1024u) {
                unsigned key = g_key[i];
                unsigned bin = key >> 16;
                if (bin > b1 && bin <= TOPBIN) {
                    unsigned pn = atomicAdd(&sh_cA, 1u);
                    if (pn < KTOP) g_A[pn] = make_uint2(key, i);
                } else if (bin == b1) {
                    unsigned pn = atomicAdd(&sh_cE, 1u);
                    if (pn < ECAP) g_E2[pn] = make_uint2(key, i);
                }
            }
            __syncthreads();
            src = g_E2; CE = min(sh_cE, (unsigned)ECAP);
            K2 = Kb; b1v = b1; cntA = min(sh_cA, (unsigned)KTOP);
        }

        // pass A: hist of key bits[8:16)
        if (t < 256u) hist[t] = 0u;
        if (t == 0u) { sh_cntG = 0u; sh_cntEq = 0u; }
        __syncthreads();
        for (unsigned e = t; e < CE; e += 1024u)
            atomicAdd(&hist[(src[e].x >> 8) & 0xFFu], 1u);
        __syncthreads();
        sufscan_find(hist, K2, &sh_bin, &sh_K);
        __syncthreads();
        unsigned bh = sh_bin, K3 = sh_K;

        // pass B: hist of low 8 bits within sub-bin bh
        if (t < 256u) hist[t] = 0u;
        __syncthreads();
        for (unsigned e = t; e < CE; e += 1024u) {
            unsigned k = src[e].x;
            if (((k >> 8) & 0xFFu) == bh) atomicAdd(&hist[k & 0xFFu], 1u);
        }
        __syncthreads();
        sufscan_find(hist, K3, &sh_bin, &sh_K);
        __syncthreads();
        unsigned VkLow = (bh << 8) | sh_bin;
        unsigned teq = sh_K;
        unsigned Vk  = (b1v << 16) | VkLow;

        // classify
        if (t < cntA) {
            uint2 a = g_A[t];
            pA[t] = ((unsigned long long)a.x << 32) | (unsigned)(~a.y);
        }
        for (unsigned e = t; e < CE; e += 1024u) {
            uint2 v = src[e];
            unsigned low = v.x & 0xFFFFu;
            if (low > VkLow) {
                unsigned p = atomicAdd(&sh_cntG, 1u);
                pA[cntA + p] = ((unsigned long long)v.x << 32) | (unsigned)(~v.y);
            } else if (low == VkLow) {
                unsigned p = atomicAdd(&sh_cntEq, 1u);
                if (p < 128u) eq[p] = v.y;
            }
        }
        __syncthreads();
        unsigned cntG = sh_cntG, cntEq = min(sh_cntEq, 128u);

        // sort ties ascending by index
        if (cntEq <= 32u) {
            if (t < 32u) {
                unsigned val = (t < cntEq) ? eq[t] : 0xFFFFFFFFu;
                #pragma unroll
                for (unsigned kk = 2; kk <= 32; kk <<= 1)
                    for (unsigned j = kk >> 1; j > 0; j >>= 1) {
                        unsigned other = __shfl_xor_sync(0xFFFFFFFFu, val, j);
                        bool up   = ((t & kk) == 0u);
                        bool lowp = ((t & j) == 0u);
                        unsigned mx = max(val, other), mn = min(val, other);
                        val = (lowp == up) ? mn : mx;
                    }
                eq[t] = val;
            }
            __syncthreads();
        } else {
            if (t < 128u && t >= cntEq) eq[t] = 0xFFFFFFFFu;
            __syncthreads();
            for (unsigned kk = 2; kk <= 128; kk <<= 1)
                for (unsigned j = kk >> 1; j > 0; j >>= 1) {
                    if (t < 128u) {
                        unsigned ixj = t ^ j;
                        if (ixj > t) {
                            unsigned a = eq[t], b = eq[ixj];
                            bool up = ((t & kk) == 0u);
                            if ((a > b) == up) { eq[t] = b; eq[ixj] = a; }
                        }
                    }
                    __syncthreads();
                }
        }
        if (t < teq)
            pA[cntA + cntG + t] = ((unsigned long long)Vk << 32) | (unsigned)(~eq[t]);
        __syncthreads();

        // bitonic 1024 descending by (key,~idx); shfl for j<32
        unsigned long long val = pA[t];
        int cur = 1;
        for (unsigned kk = 2; kk <= KTOP; kk <<= 1) {
            for (unsigned j = kk >> 1; j > 0; j >>= 1) {
                bool up   = ((t & kk) == 0u);
                bool lowp = ((t & j) == 0u);
                unsigned long long other;
                if (j >= 32u) {
                    unsigned long long* w = cur ? pB : pA;
                    w[t] = val;
                    __syncthreads();
                    other = w[t ^ j];
                    cur ^= 1;
                } else {
                    other = __shfl_xor_sync(0xFFFFFFFFu, val, j);
                }
                unsigned long long mx = (val > other) ? val : other;
                unsigned long long mn = (val > other) ? other : val;
                val = (lowp == up) ? mx : mn;
            }
        }

        unsigned key = (unsigned)(val >> 32);
        unsigned idx = ~(unsigned)val;
        int valid = (key >= (BIN0 << 16)) ? 1 : 0;
        unsigned bal = __ballot_sync(0xFFFFFFFFu, valid);
        if ((t & 31u) == 0u) g_validw[t >> 5] = bal;
        g_order[t] = idx;
        __threadfence();
        __syncthreads();
        if (t == 0u) atomicExch(&g_sync0, 1u);
    } else {
        if (t == 0u)
            while (atomicAdd(&g_sync0, 0u) == 0u) __nanosleep(128);
        __syncthreads();
        __threadfence();
    }

    // ===================== phase G: gather 16 slots per block ===============
    if (t < 128u) {
        unsigned slot = bid * 16u + (t >> 3);
        unsigned seg = t & 7u;
        unsigned idx = g_order[slot];
        const float* r = pred + (size_t)idx * 85u;
        unsigned best = __float_as_uint(__ldg(r + 5 + seg * 10));
        unsigned bi   = seg * 10u;
        #pragma unroll
        for (int j = 1; j < 10; j++) {
            unsigned v = __float_as_uint(__ldg(r + 5 + seg * 10 + j));
            if (v > best) { best = v; bi = seg * 10u + (unsigned)j; }
        }
        #pragma unroll
        for (int d = 4; d; d >>= 1) {
            unsigned ob = __shfl_down_sync(0xFFFFFFFFu, best, d, 8);
            unsigned oi = __shfl_down_sync(0xFFFFFFFFu, bi, d, 8);
            if (ob > best || (ob == best && oi < bi)) { best = ob; bi = oi; }
        }
        if (seg == 0u) {
            float cx = __ldg(r), cy = __ldg(r + 1), w = __ldg(r + 2),
                  h = __ldg(r + 3), obj = __ldg(r + 4);
            float c = __uint_as_float(best);
            float hw = __fmul_rn(w, 0.5f), hh = __fmul_rn(h, 0.5f);
            g_boxes[slot] = make_float4(__fsub_rn(cx, hw), __fsub_rn(cy, hh),
                                        __fadd_rn(cx, hw), __fadd_rn(cy, hh));
            g_info[slot]  = make_float4(obj, c, (float)bi, 0.0f);
        }
    }
    __threadfence();
    __syncthreads();
    if (t == 0u) {
        atomicAdd(&g_sync1, 1u);
        while (atomicAdd(&g_sync1, 0u) < GBLK) __nanosleep(64);
    }
    __syncthreads();
    __threadfence();

    // ===== phase I: IoU; 65536 threads = (row, blk-word, quarter) ==========
    sb[t] = g_boxes[t];
    __syncthreads();
    {
        unsigned unit = bid * 1024u + t;
        unsigned i   = unit >> 6;          // row 0..1023 (warp = one row half)
        unsigned sub = unit & 63u;
        unsigned blk = sub >> 2;           // 0..15
        unsigned q   = sub & 3u;           // quarter of the 64-col word
        float4 bi = sb[i];
        float ai = __fmul_rn(__fsub_rn(bi.z, bi.x), __fsub_rn(bi.w, bi.y));
        unsigned long long bits = 0ull;
        unsigned jbase = blk * 64u + q * 16u;
        #pragma unroll
        for (int jj = 0; jj < 16; jj++) {
            float4 bj = sb[jbase + (unsigned)jj];
            float aj = __fmul_rn(__fsub_rn(bj.z, bj.x), __fsub_rn(bj.w, bj.y));
            float ltx = fmaxf(bi.x, bj.x), lty = fmaxf(bi.y, bj.y);
            float rbx = fminf(bi.z, bj.z), rby = fminf(bi.w, bj.w);
            float wx = fmaxf(__fsub_rn(rbx, ltx), 0.0f);
            float wy = fmaxf(__fsub_rn(rby, lty), 0.0f);
            float inter = __fmul_rn(wx, wy);
            float uni = __fsub_rn(__fadd_rn(ai, aj), inter);
            float iou = __fdiv_rn(inter, fmaxf(uni, 1e-9f));
            bits |= ((unsigned long long)(iou > 0.65f)) << (q * 16u + (unsigned)jj);
        }
        bits |= __shfl_xor_sync(0xFFFFFFFFu, bits, 1);
        bits |= __shfl_xor_sync(0xFFFFFFFFu, bits, 2);
        int nz = 0;
        if (q == 0u) {
            g_M[(size_t)i * 16 + blk] = bits;
            unsigned long long selfm = (blk == (i >> 6)) ? (1ull << (i & 63u)) : 0ull;
            nz = ((bits & ~selfm) != 0ull);
        }
        unsigned bal = __ballot_sync(0xFFFFFFFFu, nz);
        if ((t & 31u) == 0u && bal)
            atomicOr(&g_rowNZ[i >> 6], 1ull << (i & 63u));
    }
    __threadfence();
    __syncthreads();
    if (t == 0u) atomicAdd(&g_sync2, 1u);
    if (bid != 0u) return;

    // ===================== phase N (block 0): NMS + output ==================
    if (t == 0u)
        while (atomicAdd(&g_sync2, 0u) < GBLK) __nanosleep(64);
    __syncthreads();
    __threadfence();

    {   // stage 128KB matrix into stride-17 smem
        const uint4* gm4 = reinterpret_cast<const uint4*>(g_M);
        #pragma unroll
        for (unsigned x4 = t; x4 < 8192u; x4 += 1024u) {
            uint4 v = gm4[x4];
            unsigned row = x4 >> 3, p = x4 & 7u;
            Ms[(size_t)row * 17u + 2u * p]      = ((unsigned long long)v.y << 32) | v.x;
            Ms[(size_t)row * 17u + 2u * p + 1u] = ((unsigned long long)v.w << 32) | v.z;
        }
    }
    if (t < 16u) {
        vmArr[t]   = (unsigned long long)g_validw[2u * t]
                   | ((unsigned long long)g_validw[2u * t + 1u] << 32);
        rowNZsh[t] = g_rowNZ[t];
        remv[t]    = 0ull;
    }
    __syncthreads();

    for (unsigned b = 0; b < 16u; b++) {
        if (t < 32u) {
            unsigned long long vmb = vmArr[b], rvb = remv[b], nzb = rowNZsh[b];
            unsigned long long avail = vmb & ~rvb;
            unsigned long long keepmask = avail & ~nzb;
            unsigned long long serialm = avail & nzb;
            unsigned rowbase = b * 64u;
            if (serialm) {
                #pragma unroll
                for (int q = 0; q < 4; q++) {
                    if (!((serialm >> (q * 16)) & 0xFFFFull)) continue;
                    unsigned long long col[16];
                    #pragma unroll
                    for (int jj = 0; jj < 16; jj++)
                        col[jj] = Ms[(size_t)(rowbase + (unsigned)(q * 16 + jj)) * 17u + b];
                    #pragma unroll
                    for (int jj = 0; jj < 16; jj++) {
                        int j = q * 16 + jj;
                        if ((serialm >> j) & 1ull) {
                            unsigned long long below = (1ull << j) - 1ull;
                            if ((keepmask & col[jj] & below) == 0ull)
                                keepmask |= 1ull << j;
                        }
                    }
                }
            }
            if (t == 0u) keepw[b] = keepmask;
        }
        __syncthreads();
        // atomic-free cross-block suppression OR
        {
            unsigned long long km = keepw[b];
            unsigned c = t >> 6, j = t & 63u;
            unsigned long long acc = ((km >> j) & 1ull)
                                   ? Ms[(size_t)(b * 64u + j) * 17u + c] : 0ull;
            #pragma unroll
            for (int off = 16; off; off >>= 1)
                acc |= __shfl_down_sync(0xFFFFFFFFu, acc, off);
            if ((t & 31u) == 0u) tmpOr[t >> 5] = acc;
        }
        __syncthreads();
        if (t < 16u) remv[t] |= tmpOr[2u * t] | tmpOr[2u * t + 1u];
        __syncthreads();
    }

    // output
    {
        unsigned slot = t;
        int keep = (int)((keepw[slot >> 6] >> (slot & 63u)) & 1ull);
        float m = keep ? 1.0f : 0.0f;
        float4 b = g_boxes[slot];
        float4 inf = g_info[slot];
        float* o = out + (size_t)slot * 7;
        o[0] = __fmul_rn(b.x, m);  o[1] = __fmul_rn(b.y, m);
        o[2] = __fmul_rn(b.z, m);  o[3] = __fmul_rn(b.w, m);
        o[4] = __fmul_rn(inf.x, m); o[5] = __fmul_rn(inf.y, m);
        o[6] = __fmul_rn(inf.z, m);
        if (keepmode == 0)
            out[KTOP * 7 + slot] = m;
        else
            ((unsigned char*)(out + KTOP * 7))[slot] = (unsigned char)keep;
    }

    // reset scratch for next graph replay
    if (t < 16u) g_rowNZ[t] = 0ull;
    if (t == 0u) { g_sync0 = 0u; g_sync1 = 0u; g_sync2 = 0u; g_cntT = 0u; }
}

// ---------------- host ----------------
extern "C" void kernel_launch(void* const* d_in, const int* in_sizes, int n_in,
                              void* d_out, int out_size) {
    const float* pred = (const float*)d_in[0];
    float* out = (float*)d_out;
    int keepmode = 0;
    if (out_size == KTOP * 7 + KTOP / 4) keepmode = 1;

    k_score<<<NROWS / (TILES * TROWS), 256>>>(pred);          // 1
    size_t rest_smem = (size_t)KTOP * 17 * 8;                 // 139264B
    cudaFuncSetAttribute(k_rest, cudaFuncAttributeMaxDynamicSharedMemorySize,
                         (int)rest_smem);
    k_rest<<<GBLK, 1024, rest_smem>>>(pred, out, keepmode);   // 2 (launch #4 overall -> ncu)
}